// round 16
// baseline (speedup 1.0000x reference)
#include <cuda_runtime.h>
#include <cstdint>

#define B 32
#define L 512
#define T 4096
#define D 384
#define D4 (D / 4)          // 96 float4 per row
#define RPT 4               // rows per thread
#define RPB 16              // rows per block (y-dim 4 x RPT)
#define TPB_TILES (T / RPB) // 256 tiles per batch
#define NTHREADS (D4 * 4)   // 384

// Scratch (no allocations allowed in kernel_launch)
__device__ int g_idx[B * T];
__device__ int g_state[B];   // 0 = not ready, 1 = idx map ready (self-resetting)
__device__ int g_done[B];    // per-batch completion counter (self-resetting)

// Single fused kernel. Block k handles output rows [k*16, k*16+16) of batch
// b = k>>8. The block owning rows [0,16) of each batch ("scanner") first
// computes the duration scan, scatters token indices into g_idx[b][*]
// (masked -> -1, tail [total,T) -> -1), publishes via flag; the other 255
// blocks of the batch spin on the flag. Flags/counters self-reset so the
// kernel is replay-deterministic.
__global__ __launch_bounds__(NTHREADS)
void lr_kernel(const float4* __restrict__ seq,
               const int*    __restrict__ dur,
               const int*    __restrict__ mask,
               float4*       __restrict__ out,
               float*        __restrict__ out_tail,
               int write_tail) {
    __shared__ int cum[L];

    const int base = blockIdx.x * RPB;      // global output row
    const int b    = base >> 12;            // batch
    const int c    = threadIdx.x;           // 0..95
    const int y    = threadIdx.y;           // 0..3
    const int tid  = y * D4 + c;
    const bool scanner = (blockIdx.x & (TPB_TILES - 1)) == 0;

    if (scanner) {
        // ---- warp 0: scan 512 durations, 16 per lane ----
        if (tid < 32) {
            const int lane = tid;
            const int t0   = lane * 16;
            const int* dp  = dur + b * L + t0;
            int run[16];
            int acc = 0;
            #pragma unroll
            for (int i = 0; i < 16; ++i) {
                acc += dp[i];               // EXPAND_SCALE=1.0 -> round(d)=d
                run[i] = acc;
            }
            int excl = acc;
            #pragma unroll
            for (int off = 1; off < 32; off <<= 1) {
                int n = __shfl_up_sync(0xFFFFFFFFu, excl, off);
                if (lane >= off) excl += n;
            }
            excl -= acc;
            #pragma unroll
            for (int i = 0; i < 16; ++i)
                cum[t0 + i] = excl + run[i];
        }
        __syncthreads();

        // ---- all 384 threads scatter + tail fill + exp_dur output ----
        const int total = cum[L - 1];
        for (int t = tid; t < L; t += NTHREADS) {
            const int end   = cum[t];
            const int start = (t > 0) ? cum[t - 1] : 0;
            const int val   = mask[b * L + t] ? -1 : t;
            for (int j = start; j < end; ++j)
                g_idx[b * T + j] = val;
            if (write_tail)
                out_tail[b * L + t] = (float)(end - start);
        }
        for (int j = total + tid; j < T; j += NTHREADS)
            g_idx[b * T + j] = -1;

        __threadfence();                    // release g_idx before flag
        __syncthreads();
        if (tid == 0)
            atomicExch(&g_state[b], 1);
    } else {
        if (tid == 0) {
            while (atomicAdd(&g_state[b], 0) == 0) { }
        }
        __syncthreads();
        __threadfence();                    // order g_idx reads after flag
    }

    // ---- gather-expand: 4 rows/thread, branchless clamped loads ----
    int idx[RPT];
    #pragma unroll
    for (int i = 0; i < RPT; ++i)
        idx[i] = g_idx[base + y + 4 * i];   // complete predicate: <0 == pad

    float4 v[RPT];
    #pragma unroll
    for (int i = 0; i < RPT; ++i) {
        const int ci = idx[i] < 0 ? 0 : idx[i];
        v[i] = seq[(b * L + ci) * D4 + c];
    }
    const float4 z = make_float4(0.f, 0.f, 0.f, 0.f);
    #pragma unroll
    for (int i = 0; i < RPT; ++i)
        if (idx[i] < 0) v[i] = z;

    #pragma unroll
    for (int i = 0; i < RPT; ++i)
        out[(base + y + 4 * i) * D4 + c] = v[i];

    // ---- self-reset for graph-replay determinism ----
    __syncthreads();
    if (tid == 0) {
        const int n = atomicAdd(&g_done[b], 1);
        if (n == TPB_TILES - 1) {           // last block of this batch
            g_state[b] = 0;
            g_done[b]  = 0;
            __threadfence();
        }
    }
}

extern "C" void kernel_launch(void* const* d_in, const int* in_sizes, int n_in,
                              void* d_out, int out_size) {
    const float* seq  = (const float*)d_in[0];
    const int*   dur  = (const int*)d_in[1];    // int64 in ref -> int32 here
    const int*   mask = (const int*)d_in[2];    // bool in ref -> int32 here
    float* out = (float*)d_out;

    const long long main_elems = (long long)B * T * D;
    const int write_tail = (out_size >= main_elems + (long long)B * L) ? 1 : 0;

    dim3 bd(D4, 4);                             // 384 threads
    lr_kernel<<<(B * T) / RPB, bd>>>((const float4*)seq, dur, mask,
                                     (float4*)out, out + main_elems,
                                     write_tail);
}

// round 17
// speedup vs baseline: 1.8663x; 1.8663x over previous
#include <cuda_runtime.h>
#include <cstdint>

#define B 32
#define L 512
#define T 4096
#define D 384
#define D4 (D / 4)          // 96 float4 per row
#define RPT 4               // rows per thread (R6 best expand config)
#define RPB 16              // rows per block
#define TILES_PER_B (T / RPB)   // 256
#define NTHREADS (D4 * 4)   // 384

// Scratch (no allocations allowed in kernel_launch)
__device__ int g_idx[B * T];
__device__ int g_state[B];   // 0 = not ready, 1 = idx map ready (self-resetting)
__device__ int g_done[B];    // per-batch gather-completion counter (self-resetting)

// Single fused kernel, producer-first grid ordering:
//   blocks 0..31            : scanners (one per batch) — guaranteed wave 1
//   blocks 32..32+8191      : gather tiles (16 rows each)
__global__ __launch_bounds__(NTHREADS)
void lr_kernel(const float4* __restrict__ seq,
               const int*    __restrict__ dur,
               const int*    __restrict__ mask,
               float4*       __restrict__ out,
               float*        __restrict__ out_tail,
               int write_tail) {
    const int c   = threadIdx.x;            // 0..95
    const int y   = threadIdx.y;            // 0..3
    const int tid = y * D4 + c;

    if (blockIdx.x < B) {
        // ================= scanner block for batch b =================
        const int b = blockIdx.x;
        __shared__ int cum[L];

        if (tid < 32) {
            const int lane = tid;
            const int t0   = lane * 16;
            const int* dp  = dur + b * L + t0;
            int run[16];
            int acc = 0;
            #pragma unroll
            for (int i = 0; i < 16; ++i) {
                acc += dp[i];               // EXPAND_SCALE=1.0 -> round(d)=d
                run[i] = acc;
            }
            int excl = acc;
            #pragma unroll
            for (int off = 1; off < 32; off <<= 1) {
                int n = __shfl_up_sync(0xFFFFFFFFu, excl, off);
                if (lane >= off) excl += n;
            }
            excl -= acc;
            #pragma unroll
            for (int i = 0; i < 16; ++i)
                cum[t0 + i] = excl + run[i];
        }
        __syncthreads();

        const int total = cum[L - 1];
        for (int t = tid; t < L; t += NTHREADS) {
            const int end   = cum[t];
            const int start = (t > 0) ? cum[t - 1] : 0;
            const int val   = mask[b * L + t] ? -1 : t;
            for (int j = start; j < end; ++j)
                g_idx[b * T + j] = val;
            if (write_tail)
                out_tail[b * L + t] = (float)(end - start);
        }
        for (int j = total + tid; j < T; j += NTHREADS)
            g_idx[b * T + j] = -1;

        __threadfence();                    // release g_idx before flag
        __syncthreads();
        if (tid == 0)
            atomicExch(&g_state[b], 1);
        return;
    }

    // ================= gather block =================
    const int k    = blockIdx.x - B;        // tile id 0..8191
    const int base = k * RPB;               // global output row
    const int b    = base >> 12;            // batch

    if (tid == 0) {
        // acquire-poll; scanners are wave-1 so this spins ~scan time at most
        int s;
        for (;;) {
            asm volatile("ld.acquire.gpu.global.b32 %0, [%1];"
                         : "=r"(s) : "l"(&g_state[b]) : "memory");
            if (s) break;
            __nanosleep(64);
        }
    }
    __syncthreads();

    int idx[RPT];
    #pragma unroll
    for (int i = 0; i < RPT; ++i)
        idx[i] = g_idx[base + y + 4 * i];   // complete predicate: <0 == pad

    float4 v[RPT];
    #pragma unroll
    for (int i = 0; i < RPT; ++i) {
        const int ci = idx[i] < 0 ? 0 : idx[i];
        v[i] = seq[(b * L + ci) * D4 + c];
    }
    const float4 z = make_float4(0.f, 0.f, 0.f, 0.f);
    #pragma unroll
    for (int i = 0; i < RPT; ++i)
        if (idx[i] < 0) v[i] = z;

    #pragma unroll
    for (int i = 0; i < RPT; ++i)
        out[(base + y + 4 * i) * D4 + c] = v[i];

    // ---- self-reset for graph-replay determinism ----
    __syncthreads();
    if (tid == 0) {
        const int n = atomicAdd(&g_done[b], 1);
        if (n == TILES_PER_B - 1) {         // last gather block of this batch
            g_state[b] = 0;
            g_done[b]  = 0;
            __threadfence();
        }
    }
}

extern "C" void kernel_launch(void* const* d_in, const int* in_sizes, int n_in,
                              void* d_out, int out_size) {
    const float* seq  = (const float*)d_in[0];
    const int*   dur  = (const int*)d_in[1];    // int64 in ref -> int32 here
    const int*   mask = (const int*)d_in[2];    // bool in ref -> int32 here
    float* out = (float*)d_out;

    const long long main_elems = (long long)B * T * D;
    const int write_tail = (out_size >= main_elems + (long long)B * L) ? 1 : 0;

    dim3 bd(D4, 4);                             // 384 threads
    lr_kernel<<<B + (B * T) / RPB, bd>>>((const float4*)seq, dur, mask,
                                         (float4*)out, out + main_elems,
                                         write_tail);
}